// round 10
// baseline (speedup 1.0000x reference)
#include <cuda_runtime.h>
#include <cuda_bf16.h>
#include <cstdint>

#define N_TOK 4096
#define DM    512
#define NH    8
#define DKH   64
#define DFF   2048

// ---------------- scratch (device globals; no runtime allocation) ----------
__device__ float g_Q[N_TOK * DM];
__device__ float g_K[N_TOK * DM];
__device__ float g_V[N_TOK * DM];
__device__ float g_ctx[N_TOK * DM];
__device__ float g_tmp[N_TOK * DM];
__device__ float g_h1[N_TOK * DM];
__device__ float g_ff[(size_t)N_TOK * DFF];

// bf16 hi/lo planes for GEMMs
__device__ __nv_bfloat16 g_hb_hi[N_TOK * DM],  g_hb_lo[N_TOK * DM];
__device__ __nv_bfloat16 g_cx_hi[N_TOK * DM],  g_cx_lo[N_TOK * DM];
__device__ __nv_bfloat16 g_h1_hi[N_TOK * DM],  g_h1_lo[N_TOK * DM];
__device__ __nv_bfloat16 g_ff_hi[(size_t)N_TOK * DFF], g_ff_lo[(size_t)N_TOK * DFF];
#define WOFF_Q  0
#define WOFF_K  (512 * 512)
#define WOFF_V  (2 * 512 * 512)
#define WOFF_O  (3 * 512 * 512)
#define WOFF_1  (4 * 512 * 512)
#define WOFF_2  (4 * 512 * 512 + 2048 * 512)
#define WTOT    (4 * 512 * 512 + 2 * 2048 * 512)
__device__ __nv_bfloat16 g_w_hi[WTOT], g_w_lo[WTOT];

// attention: per-head bf16 planes [h][tok][64], V transposed [h][d][tok]
__device__ __nv_bfloat16 g_qs_hi[NH * N_TOK * DKH], g_qs_lo[NH * N_TOK * DKH];
__device__ __nv_bfloat16 g_ks_hi[NH * N_TOK * DKH], g_ks_lo[NH * N_TOK * DKH];
__device__ __nv_bfloat16 g_vt[NH * DKH * N_TOK];
// adjacency bitmask (diag folded in): [tok][64] uint64
__device__ unsigned long long g_adjb[N_TOK * (N_TOK / 64)];

// ===================== low-level helpers ==================================
__device__ __forceinline__ uint32_t smem_u32(const void* p) {
    uint32_t a;
    asm("{ .reg .u64 t; cvta.to.shared.u64 t, %1; cvt.u32.u64 %0, t; }"
        : "=r"(a) : "l"(p));
    return a;
}
__device__ __forceinline__ void cp16(uint32_t dst, const void* src) {
    asm volatile("cp.async.cg.shared.global [%0], [%1], 16;" :: "r"(dst), "l"(src));
}
__device__ __forceinline__ void ldm_x4(uint32_t* r, uint32_t addr) {
    asm volatile("ldmatrix.sync.aligned.m8n8.x4.shared.b16 {%0,%1,%2,%3}, [%4];"
                 : "=r"(r[0]), "=r"(r[1]), "=r"(r[2]), "=r"(r[3]) : "r"(addr));
}
__device__ __forceinline__ void mma_bf16(float* d, const uint32_t* a, const uint32_t* b) {
    asm volatile("mma.sync.aligned.m16n8k16.row.col.f32.bf16.bf16.f32 "
                 "{%0,%1,%2,%3},{%4,%5,%6,%7},{%8,%9},{%0,%1,%2,%3};"
                 : "+f"(d[0]), "+f"(d[1]), "+f"(d[2]), "+f"(d[3])
                 : "r"(a[0]), "r"(a[1]), "r"(a[2]), "r"(a[3]),
                   "r"(b[0]), "r"(b[1]));
}
// 2^(s-8) without MUFU; valid for s in [-110, 100]
__device__ __forceinline__ float fexp2b(float s) {
    const float C1 = 12582904.0f;                 // 1.5*2^23 - 8
    float t  = s + C1;
    float v  = t - C1;
    float zf = s - v;
    int   zi = __float_as_int(t) - 0x4B400000;
    float p = fmaf(zf, 0.00961813f, 0.05550411f);
    p = fmaf(zf, p, 0.24022651f);
    p = fmaf(zf, p, 0.69314718f);
    p = fmaf(zf, p, 1.0f);
    return __int_as_float(__float_as_int(p) + (zi << 23));
}

// ===================== fp32 -> bf16 hi/lo conversion (flat) ================
__global__ __launch_bounds__(256) void convert_split(const float* __restrict__ in,
                                                     __nv_bfloat16* __restrict__ hi,
                                                     __nv_bfloat16* __restrict__ lo,
                                                     int n)
{
    int i = (blockIdx.x * 256 + threadIdx.x) * 4;
    if (i >= n) return;
    float4 v = *reinterpret_cast<const float4*>(in + i);
    __nv_bfloat16 hx = __float2bfloat16(v.x), hy = __float2bfloat16(v.y);
    __nv_bfloat16 hz = __float2bfloat16(v.z), hw = __float2bfloat16(v.w);
    __nv_bfloat162 h0; h0.x = hx; h0.y = hy;
    __nv_bfloat162 h1; h1.x = hz; h1.y = hw;
    __nv_bfloat162 l0, l1;
    l0.x = __float2bfloat16(v.x - __bfloat162float(hx));
    l0.y = __float2bfloat16(v.y - __bfloat162float(hy));
    l1.x = __float2bfloat16(v.z - __bfloat162float(hz));
    l1.y = __float2bfloat16(v.w - __bfloat162float(hw));
    *reinterpret_cast<__nv_bfloat162*>(hi + i)     = h0;
    *reinterpret_cast<__nv_bfloat162*>(hi + i + 2) = h1;
    *reinterpret_cast<__nv_bfloat162*>(lo + i)     = l0;
    *reinterpret_cast<__nv_bfloat162*>(lo + i + 2) = l1;
}

// fp32 [tok][512] -> per-head split planes [h][tok][64], optional scale
__global__ __launch_bounds__(256) void convert_split_heads(const float* __restrict__ in,
                                                           __nv_bfloat16* __restrict__ hi,
                                                           __nv_bfloat16* __restrict__ lo,
                                                           float scale)
{
    int i = (blockIdx.x * 256 + threadIdx.x) * 4;
    int tok = i >> 9, col = i & 511;
    int h = col >> 6, d = col & 63;
    size_t dst = (size_t)h * (N_TOK * DKH) + (size_t)tok * DKH + d;
    float4 v = *reinterpret_cast<const float4*>(in + i);
    v.x *= scale; v.y *= scale; v.z *= scale; v.w *= scale;
    __nv_bfloat16 hx = __float2bfloat16(v.x), hy = __float2bfloat16(v.y);
    __nv_bfloat16 hz = __float2bfloat16(v.z), hw = __float2bfloat16(v.w);
    __nv_bfloat162 h0; h0.x = hx; h0.y = hy;
    __nv_bfloat162 h1; h1.x = hz; h1.y = hw;
    __nv_bfloat162 l0, l1;
    l0.x = __float2bfloat16(v.x - __bfloat162float(hx));
    l0.y = __float2bfloat16(v.y - __bfloat162float(hy));
    l1.x = __float2bfloat16(v.z - __bfloat162float(hz));
    l1.y = __float2bfloat16(v.w - __bfloat162float(hw));
    *reinterpret_cast<__nv_bfloat162*>(hi + dst)     = h0;
    *reinterpret_cast<__nv_bfloat162*>(hi + dst + 2) = h1;
    *reinterpret_cast<__nv_bfloat162*>(lo + dst)     = l0;
    *reinterpret_cast<__nv_bfloat162*>(lo + dst + 2) = l1;
}

// V fp32 [tok][512] -> bf16 transposed [h][d][tok]
__global__ __launch_bounds__(256) void convert_v_t(const float* __restrict__ V,
                                                   __nv_bfloat16* __restrict__ vt)
{
    __shared__ float sm[64][65];
    const int h = blockIdx.y, t0 = blockIdx.x * 64;
    const int tid = threadIdx.x;
    for (int i = tid; i < 1024; i += 256) {
        int r = i >> 4, c4 = (i & 15) * 4;
        float4 v = *reinterpret_cast<const float4*>(&V[(size_t)(t0 + r) * DM + h * DKH + c4]);
        sm[c4][r] = v.x; sm[c4 + 1][r] = v.y; sm[c4 + 2][r] = v.z; sm[c4 + 3][r] = v.w;
    }
    __syncthreads();
    for (int i = tid; i < 2048; i += 256) {
        int d = i >> 5, pr = i & 31;
        __nv_bfloat162 b = __floats2bfloat162_rn(sm[d][2 * pr], sm[d][2 * pr + 1]);
        *reinterpret_cast<__nv_bfloat162*>(
            vt + (size_t)h * (DKH * N_TOK) + (size_t)d * N_TOK + t0 + 2 * pr) = b;
    }
}

// adj int32 -> bitmask, diag folded in
__global__ __launch_bounds__(256) void pack_adj(const int* __restrict__ adj,
                                                unsigned long long* __restrict__ bits)
{
    int gid = blockIdx.x * 256 + threadIdx.x;
    int r = gid >> 6, w = gid & 63;
    const int4* p = reinterpret_cast<const int4*>(adj + (size_t)r * N_TOK + w * 64);
    unsigned long long b = 0;
    #pragma unroll
    for (int i = 0; i < 16; i++) {
        int4 a = p[i];
        if (a.x) b |= 1ull << (i * 4 + 0);
        if (a.y) b |= 1ull << (i * 4 + 1);
        if (a.z) b |= 1ull << (i * 4 + 2);
        if (a.w) b |= 1ull << (i * 4 + 3);
    }
    if ((r >> 6) == w) b |= 1ull << (r & 63);
    bits[gid] = b;
}

// ===================== pipelined split-bf16 GEMM (attention-style) ========
// C[m,n] = sum_k A[m,k]*B[n,k] + bias[n]; tile 64x64; 4 warps x (16m x 64n);
// k-chunks of 32, 2-stage cp.async pipeline. SROW=80 conflict-free layout.
#define SROW 80

__device__ __forceinline__ void gemm_load_chunk(
    uint32_t sa_hi, uint32_t sa_lo, uint32_t sb_hi, uint32_t sb_lo,
    const __nv_bfloat16* gA_hi, const __nv_bfloat16* gA_lo,
    const __nv_bfloat16* gB_hi, const __nv_bfloat16* gB_lo,
    int K, int c, int tid)
{
    const int u  = tid & 3;
    const int gk = c * 32 + u * 8;
    #pragma unroll
    for (int i = 0; i < 2; i++) {
        const int row = (tid >> 2) + i * 32;
        const uint32_t doff = (uint32_t)(row * SROW + u * 16);
        const size_t go = (size_t)row * K + gk;
        cp16(sa_hi + doff, gA_hi + go);
        cp16(sa_lo + doff, gA_lo + go);
        cp16(sb_hi + doff, gB_hi + go);
        cp16(sb_lo + doff, gB_lo + go);
    }
    asm volatile("cp.async.commit_group;");
}

template <bool RELU>
__device__ __forceinline__ void gemm_mma_body(const __nv_bfloat16* __restrict__ Ahi,
                                              const __nv_bfloat16* __restrict__ Alo,
                                              const __nv_bfloat16* __restrict__ Bhi,
                                              const __nv_bfloat16* __restrict__ Blo,
                                              const float* __restrict__ bias,
                                              float* __restrict__ C,
                                              int Nn, int K)
{
    __shared__ __align__(128) uint8_t s_ahi[2][64 * SROW];
    __shared__ __align__(128) uint8_t s_alo[2][64 * SROW];
    __shared__ __align__(128) uint8_t s_bhi[2][64 * SROW];
    __shared__ __align__(128) uint8_t s_blo[2][64 * SROW];

    const int tid = threadIdx.x, lid = tid & 31, wid = tid >> 5;
    const int wm  = wid * 16;
    const int m0  = blockIdx.y * 64, n0 = blockIdx.x * 64;

    const uint32_t sa_hi[2] = {smem_u32(s_ahi[0]), smem_u32(s_ahi[1])};
    const uint32_t sa_lo[2] = {smem_u32(s_alo[0]), smem_u32(s_alo[1])};
    const uint32_t sb_hi[2] = {smem_u32(s_bhi[0]), smem_u32(s_bhi[1])};
    const uint32_t sb_lo[2] = {smem_u32(s_blo[0]), smem_u32(s_blo[1])};

    const __nv_bfloat16* gA_hi = Ahi + (size_t)m0 * K;
    const __nv_bfloat16* gA_lo = Alo + (size_t)m0 * K;
    const __nv_bfloat16* gB_hi = Bhi + (size_t)n0 * K;
    const __nv_bfloat16* gB_lo = Blo + (size_t)n0 * K;

    const int a_row = lid & 15;
    const int a_sel = lid >> 4;
    const int b_row = ((lid >> 4) & 1) * 8 + (lid & 7);
    const int b_sel = (lid >> 3) & 1;

    float acc[8][4] = {};

    const int nch = K >> 5;
    gemm_load_chunk(sa_hi[0], sa_lo[0], sb_hi[0], sb_lo[0],
                    gA_hi, gA_lo, gB_hi, gB_lo, K, 0, tid);
    if (nch > 1)
        gemm_load_chunk(sa_hi[1], sa_lo[1], sb_hi[1], sb_lo[1],
                        gA_hi, gA_lo, gB_hi, gB_lo, K, 1, tid);

    for (int c = 0; c < nch; c++) {
        if (c == nch - 1) asm volatile("cp.async.wait_group 0;" ::: "memory");
        else              asm volatile("cp.async.wait_group 1;" ::: "memory");
        __syncthreads();

        const int st = c & 1;
        #pragma unroll
        for (int ks = 0; ks < 2; ks++) {
            uint32_t ah[4], al[4];
            const uint32_t aoff = (uint32_t)((wm + a_row) * SROW + (ks * 2 + a_sel) * 16);
            ldm_x4(ah, sa_hi[st] + aoff);
            ldm_x4(al, sa_lo[st] + aoff);
            #pragma unroll
            for (int t = 0; t < 4; t++) {
                uint32_t bh[4], bl[4];
                const uint32_t boff = (uint32_t)((t * 16 + b_row) * SROW
                                                 + (ks * 2 + b_sel) * 16);
                ldm_x4(bh, sb_hi[st] + boff);
                ldm_x4(bl, sb_lo[st] + boff);
                #pragma unroll
                for (int t2 = 0; t2 < 2; t2++) {
                    float* d = acc[t * 2 + t2];
                    mma_bf16(d, ah, &bh[t2 * 2]);
                    mma_bf16(d, ah, &bl[t2 * 2]);
                    mma_bf16(d, al, &bh[t2 * 2]);
                }
            }
        }
        __syncthreads();
        if (c + 2 < nch)
            gemm_load_chunk(sa_hi[st], sa_lo[st], sb_hi[st], sb_lo[st],
                            gA_hi, gA_lo, gB_hi, gB_lo, K, c + 2, tid);
    }

    // epilogue (attention-style fragment layout)
    const int rr0   = m0 + wm + (lid >> 2);
    const int cbase = n0 + (lid & 3) * 2;
    #pragma unroll
    for (int f = 0; f < 8; f++) {
        const int col = cbase + f * 8;
        const float bx = bias[col], by = bias[col + 1];
        float2 v0, v1;
        v0.x = acc[f][0] + bx; v0.y = acc[f][1] + by;
        v1.x = acc[f][2] + bx; v1.y = acc[f][3] + by;
        if (RELU) {
            v0.x = fmaxf(v0.x, 0.0f); v0.y = fmaxf(v0.y, 0.0f);
            v1.x = fmaxf(v1.x, 0.0f); v1.y = fmaxf(v1.y, 0.0f);
        }
        *reinterpret_cast<float2*>(C + (size_t)rr0 * Nn + col)       = v0;
        *reinterpret_cast<float2*>(C + (size_t)(rr0 + 8) * Nn + col) = v1;
    }
}

template <bool RELU>
__global__ __launch_bounds__(128) void gemm_mma(const __nv_bfloat16* __restrict__ Ahi,
                                                const __nv_bfloat16* __restrict__ Alo,
                                                const __nv_bfloat16* __restrict__ Bhi,
                                                const __nv_bfloat16* __restrict__ Blo,
                                                const float* __restrict__ bias,
                                                float* __restrict__ C,
                                                int Nn, int K)
{
    gemm_mma_body<RELU>(Ahi, Alo, Bhi, Blo, bias, C, Nn, K);
}

__global__ __launch_bounds__(128) void gemm_mma_qkv(const __nv_bfloat16* __restrict__ Ahi,
                                                    const __nv_bfloat16* __restrict__ Alo,
                                                    const float* __restrict__ bq,
                                                    const float* __restrict__ bk,
                                                    const float* __restrict__ bv,
                                                    float* __restrict__ Qo,
                                                    float* __restrict__ Ko,
                                                    float* __restrict__ Vo)
{
    const __nv_bfloat16* whi; const __nv_bfloat16* wlo;
    const float* bias; float* C;
    if (blockIdx.z == 0)      { whi = g_w_hi + WOFF_Q; wlo = g_w_lo + WOFF_Q; bias = bq; C = Qo; }
    else if (blockIdx.z == 1) { whi = g_w_hi + WOFF_K; wlo = g_w_lo + WOFF_K; bias = bk; C = Ko; }
    else                      { whi = g_w_hi + WOFF_V; wlo = g_w_lo + WOFF_V; bias = bv; C = Vo; }
    gemm_mma_body<false>(Ahi, Alo, whi, wlo, bias, C, DM, DM);
}

// ===================== tensor-core flash attention (unchanged R7) =========
__global__ __launch_bounds__(128) void attn_mma(
    const __nv_bfloat16* __restrict__ qhi, const __nv_bfloat16* __restrict__ qlo,
    const __nv_bfloat16* __restrict__ khi, const __nv_bfloat16* __restrict__ klo,
    const __nv_bfloat16* __restrict__ vt,
    const unsigned long long* __restrict__ adjb,
    float* __restrict__ ctx)
{
    __shared__ __align__(128) uint8_t s_khi[2 * 64 * SROW];
    __shared__ __align__(128) uint8_t s_klo[2 * 64 * SROW];
    __shared__ __align__(128) uint8_t s_vt [2 * 64 * SROW];

    const int tid = threadIdx.x, lid = tid & 31, wid = tid >> 5;
    const int h = blockIdx.y, q0 = blockIdx.x * 64;
    const int wm = wid * 16;
    const size_t hoff = (size_t)h * (N_TOK * DKH);

    const uint32_t skhi = smem_u32(s_khi), sklo = smem_u32(s_klo), svt = smem_u32(s_vt);

    uint32_t qa_h[4][4], qa_l[4][4];
    const int rr0 = q0 + wm + (lid >> 2);
    {
        const int cc = (lid & 3) * 2;
        #pragma unroll
        for (int ks = 0; ks < 4; ks++) {
            const size_t o0 = hoff + (size_t)rr0 * 64 + ks * 16 + cc;
            const size_t o1 = hoff + (size_t)(rr0 + 8) * 64 + ks * 16 + cc;
            qa_h[ks][0] = *reinterpret_cast<const uint32_t*>(qhi + o0);
            qa_h[ks][1] = *reinterpret_cast<const uint32_t*>(qhi + o1);
            qa_h[ks][2] = *reinterpret_cast<const uint32_t*>(qhi + o0 + 8);
            qa_h[ks][3] = *reinterpret_cast<const uint32_t*>(qhi + o1 + 8);
            qa_l[ks][0] = *reinterpret_cast<const uint32_t*>(qlo + o0);
            qa_l[ks][1] = *reinterpret_cast<const uint32_t*>(qlo + o1);
            qa_l[ks][2] = *reinterpret_cast<const uint32_t*>(qlo + o0 + 8);
            qa_l[ks][3] = *reinterpret_cast<const uint32_t*>(qlo + o1 + 8);
        }
    }

    const int b_row = ((lid >> 4) & 1) * 8 + (lid & 7);
    const int b_sel = (lid >> 3) & 1;

    float o_acc[8][4] = {};
    float lsum0 = 0.0f, lsum1 = 0.0f;

    {
        #pragma unroll
        for (int i = 0; i < 4; i++) {
            const int idx = tid + i * 128;
            const int row = idx >> 3, ch = (idx >> 2) & 1, u = idx & 3;
            const uint32_t doff = (uint32_t)((ch * 64 + row) * SROW + u * 16);
            cp16(skhi + doff, khi + hoff + (size_t)row * 64 + ch * 32 + u * 8);
            cp16(sklo + doff, klo + hoff + (size_t)row * 64 + ch * 32 + u * 8);
            cp16(svt  + doff, vt  + hoff + (size_t)row * N_TOK + ch * 32 + u * 8);
        }
        asm volatile("cp.async.commit_group;");
    }

    for (int kb = 0; kb < N_TOK / 64; kb++) {
        asm volatile("cp.async.wait_group 0;" ::: "memory");
        __syncthreads();

        float sc[8][4] = {};
        #pragma unroll
        for (int ks = 0; ks < 4; ks++) {
            const uint32_t base = (uint32_t)(((ks >> 1) * 64 + b_row) * SROW
                                             + ((ks & 1) * 2 + b_sel) * 16);
            #pragma unroll
            for (int t = 0; t < 4; t++) {
                uint32_t bh[4], bl[4];
                ldm_x4(bh, skhi + base + t * 16 * SROW);
                ldm_x4(bl, sklo + base + t * 16 * SROW);
                #pragma unroll
                for (int t2 = 0; t2 < 2; t2++) {
                    float* d = sc[t * 2 + t2];
                    mma_bf16(d, qa_h[ks], &bh[t2 * 2]);
                    mma_bf16(d, qa_h[ks], &bl[t2 * 2]);
                    mma_bf16(d, qa_l[ks], &bh[t2 * 2]);
                }
            }
        }

        const unsigned long long w0 = adjb[(size_t)rr0 * 64 + kb];
        const unsigned long long w1 = adjb[(size_t)(rr0 + 8) * 64 + kb];
        uint32_t pa[4][4];
        #pragma unroll
        for (int f = 0; f < 8; f++) {
            const int cb = f * 8 + (lid & 3) * 2;
            const float s0 = ((w0 >> cb) & 1)       ? sc[f][0] : -102.0f;
            const float s1 = ((w0 >> (cb + 1)) & 1) ? sc[f][1] : -102.0f;
            const float s2 = ((w1 >> cb) & 1)       ? sc[f][2] : -102.0f;
            const float s3 = ((w1 >> (cb + 1)) & 1) ? sc[f][3] : -102.0f;
            const float p0 = fexp2b(s0), p1 = fexp2b(s1);
            const float p2 = fexp2b(s2), p3 = fexp2b(s3);
            lsum0 += p0 + p1; lsum1 += p2 + p3;
            __nv_bfloat162 x01 = __floats2bfloat162_rn(p0, p1);
            __nv_bfloat162 x23 = __floats2bfloat162_rn(p2, p3);
            const int j = f >> 1, oo = (f & 1) * 2;
            pa[j][oo]     = *reinterpret_cast<uint32_t*>(&x01);
            pa[j][oo + 1] = *reinterpret_cast<uint32_t*>(&x23);
        }

        #pragma unroll
        for (int ks = 0; ks < 4; ks++) {
            const uint32_t base = (uint32_t)(((ks >> 1) * 64 + b_row) * SROW
                                             + ((ks & 1) * 2 + b_sel) * 16);
            #pragma unroll
            for (int t = 0; t < 4; t++) {
                uint32_t bv[4];
                ldm_x4(bv, svt + base + t * 16 * SROW);
                mma_bf16(o_acc[t * 2],     pa[ks], &bv[0]);
                mma_bf16(o_acc[t * 2 + 1], pa[ks], &bv[2]);
            }
        }

        __syncthreads();
        if (kb < N_TOK / 64 - 1) {
            const int k0 = (kb + 1) * 64;
            #pragma unroll
            for (int i = 0; i < 4; i++) {
                const int idx = tid + i * 128;
                const int row = idx >> 3, ch = (idx >> 2) & 1, u = idx & 3;
                const uint32_t doff = (uint32_t)((ch * 64 + row) * SROW + u * 16);
                cp16(skhi + doff, khi + hoff + (size_t)(k0 + row) * 64 + ch * 32 + u * 8);
                cp16(sklo + doff, klo + hoff + (size_t)(k0 + row) * 64 + ch * 32 + u * 8);
                cp16(svt  + doff, vt  + hoff + (size_t)row * N_TOK + k0 + ch * 32 + u * 8);
            }
            asm volatile("cp.async.commit_group;");
        }
    }

    lsum0 += __shfl_xor_sync(0xffffffffu, lsum0, 1);
    lsum0 += __shfl_xor_sync(0xffffffffu, lsum0, 2);
    lsum1 += __shfl_xor_sync(0xffffffffu, lsum1, 1);
    lsum1 += __shfl_xor_sync(0xffffffffu, lsum1, 2);
    const float inv0 = 1.0f / lsum0, inv1 = 1.0f / lsum1;
    const int col0 = h * DKH + (lid & 3) * 2;
    #pragma unroll
    for (int f = 0; f < 8; f++) {
        float2 v0 = make_float2(o_acc[f][0] * inv0, o_acc[f][1] * inv0);
        float2 v1 = make_float2(o_acc[f][2] * inv1, o_acc[f][3] * inv1);
        *reinterpret_cast<float2*>(ctx + (size_t)rr0 * DM + col0 + f * 8)       = v0;
        *reinterpret_cast<float2*>(ctx + (size_t)(rr0 + 8) * DM + col0 + f * 8) = v1;
    }
}

// ---------------------------------------------------------------------------
// out = LayerNorm(x + r) * g + b
// ---------------------------------------------------------------------------
__global__ __launch_bounds__(128) void ln_kernel(const float* __restrict__ x,
                                                 const float* __restrict__ r,
                                                 const float* __restrict__ g,
                                                 const float* __restrict__ b,
                                                 float* __restrict__ out)
{
    __shared__ float ws[4], ws2[4];
    const int row = blockIdx.x;
    const int tid = threadIdx.x;
    const int col = tid * 4;

    float4 xv = *reinterpret_cast<const float4*>(&x[(size_t)row * DM + col]);
    float4 rv = *reinterpret_cast<const float4*>(&r[(size_t)row * DM + col]);
    float v[4] = {xv.x + rv.x, xv.y + rv.y, xv.z + rv.z, xv.w + rv.w};

    float s = 0.0f, s2 = 0.0f;
    #pragma unroll
    for (int c = 0; c < 4; c++) { s += v[c]; s2 = fmaf(v[c], v[c], s2); }
    #pragma unroll
    for (int off = 16; off >= 1; off >>= 1) {
        s  += __shfl_xor_sync(0xffffffffu, s,  off);
        s2 += __shfl_xor_sync(0xffffffffu, s2, off);
    }
    const int wid = tid >> 5;
    if ((tid & 31) == 0) { ws[wid] = s; ws2[wid] = s2; }
    __syncthreads();
    const float S  = ws[0] + ws[1] + ws[2] + ws[3];
    const float S2 = ws2[0] + ws2[1] + ws2[2] + ws2[3];
    const float mean = S * (1.0f / DM);
    const float var  = S2 * (1.0f / DM) - mean * mean;
    const float rstd = rsqrtf(var + 1e-5f);

    float4 gv = *reinterpret_cast<const float4*>(&g[col]);
    float4 bv = *reinterpret_cast<const float4*>(&b[col]);
    float gr[4] = {gv.x, gv.y, gv.z, gv.w};
    float br[4] = {bv.x, bv.y, bv.z, bv.w};
    float4 ov; float* op = &ov.x;
    #pragma unroll
    for (int c = 0; c < 4; c++)
        op[c] = (v[c] - mean) * rstd * gr[c] + br[c];
    *reinterpret_cast<float4*>(&out[(size_t)row * DM + col]) = ov;
}

// ---------------------------------------------------------------------------
extern "C" void kernel_launch(void* const* d_in, const int* in_sizes, int n_in,
                              void* d_out, int out_size)
{
    const float* h    = (const float*)d_in[0];
    const int*   adj  = (const int*)d_in[1];
    const float* Wq   = (const float*)d_in[2];
    const float* bq   = (const float*)d_in[3];
    const float* Wk   = (const float*)d_in[4];
    const float* bk   = (const float*)d_in[5];
    const float* Wv   = (const float*)d_in[6];
    const float* bv   = (const float*)d_in[7];
    const float* Wo   = (const float*)d_in[8];
    const float* bo   = (const float*)d_in[9];
    const float* W1   = (const float*)d_in[10];
    const float* b1   = (const float*)d_in[11];
    const float* W2   = (const float*)d_in[12];
    const float* b2   = (const float*)d_in[13];
    const float* ln1g = (const float*)d_in[14];
    const float* ln1b = (const float*)d_in[15];
    const float* ln2g = (const float*)d_in[16];
    const float* ln2b = (const float*)d_in[17];
    float* out = (float*)d_out;

    float *Qd, *Kd, *Vd, *ctx, *tmp, *h1, *ff;
    cudaGetSymbolAddress((void**)&Qd,  g_Q);
    cudaGetSymbolAddress((void**)&Kd,  g_K);
    cudaGetSymbolAddress((void**)&Vd,  g_V);
    cudaGetSymbolAddress((void**)&ctx, g_ctx);
    cudaGetSymbolAddress((void**)&tmp, g_tmp);
    cudaGetSymbolAddress((void**)&h1,  g_h1);
    cudaGetSymbolAddress((void**)&ff,  g_ff);

    __nv_bfloat16 *hb_hi, *hb_lo, *cx_hi, *cx_lo, *h1_hi, *h1_lo, *ff_hi, *ff_lo, *w_hi, *w_lo;
    __nv_bfloat16 *qs_hi, *qs_lo, *ks_hi, *ks_lo, *vtp;
    unsigned long long* adjb;
    cudaGetSymbolAddress((void**)&hb_hi, g_hb_hi);
    cudaGetSymbolAddress((void**)&hb_lo, g_hb_lo);
    cudaGetSymbolAddress((void**)&cx_hi, g_cx_hi);
    cudaGetSymbolAddress((void**)&cx_lo, g_cx_lo);
    cudaGetSymbolAddress((void**)&h1_hi, g_h1_hi);
    cudaGetSymbolAddress((void**)&h1_lo, g_h1_lo);
    cudaGetSymbolAddress((void**)&ff_hi, g_ff_hi);
    cudaGetSymbolAddress((void**)&ff_lo, g_ff_lo);
    cudaGetSymbolAddress((void**)&w_hi,  g_w_hi);
    cudaGetSymbolAddress((void**)&w_lo,  g_w_lo);
    cudaGetSymbolAddress((void**)&qs_hi, g_qs_hi);
    cudaGetSymbolAddress((void**)&qs_lo, g_qs_lo);
    cudaGetSymbolAddress((void**)&ks_hi, g_ks_hi);
    cudaGetSymbolAddress((void**)&ks_lo, g_ks_lo);
    cudaGetSymbolAddress((void**)&vtp,   g_vt);
    cudaGetSymbolAddress((void**)&adjb,  g_adjb);

    const int ACT = N_TOK * DM;
    const int WSQ = 512 * 512;
    const int WFF = 2048 * 512;
    const int FFE = N_TOK * DFF;
    const float QSCALE = 1.4426950408889634f / 8.0f;   // log2(e)/sqrt(d_k)

    pack_adj<<<(N_TOK * 64) / 256, 256>>>(adj, adjb);
    convert_split<<<ACT / 1024, 256>>>(h,  hb_hi, hb_lo, ACT);
    convert_split<<<WSQ / 1024, 256>>>(Wq, w_hi + WOFF_Q, w_lo + WOFF_Q, WSQ);
    convert_split<<<WSQ / 1024, 256>>>(Wk, w_hi + WOFF_K, w_lo + WOFF_K, WSQ);
    convert_split<<<WSQ / 1024, 256>>>(Wv, w_hi + WOFF_V, w_lo + WOFF_V, WSQ);
    convert_split<<<WSQ / 1024, 256>>>(Wo, w_hi + WOFF_O, w_lo + WOFF_O, WSQ);
    convert_split<<<WFF / 1024, 256>>>(W1, w_hi + WOFF_1, w_lo + WOFF_1, WFF);
    convert_split<<<WFF / 1024, 256>>>(W2, w_hi + WOFF_2, w_lo + WOFF_2, WFF);

    const dim3 blk(128);
    const dim3 gQKV(DM / 64, N_TOK / 64, 3);
    const dim3 gP(DM / 64, N_TOK / 64);
    const dim3 gF1(DFF / 64, N_TOK / 64);

    gemm_mma_qkv<<<gQKV, blk>>>(hb_hi, hb_lo, bq, bk, bv, Qd, Kd, Vd);

    convert_split_heads<<<ACT / 1024, 256>>>(Qd, qs_hi, qs_lo, QSCALE);
    convert_split_heads<<<ACT / 1024, 256>>>(Kd, ks_hi, ks_lo, 1.0f);
    convert_v_t<<<dim3(N_TOK / 64, NH), 256>>>(Vd, vtp);

    attn_mma<<<dim3(N_TOK / 64, NH), blk>>>(qs_hi, qs_lo, ks_hi, ks_lo, vtp, adjb, ctx);

    convert_split<<<ACT / 1024, 256>>>(ctx, cx_hi, cx_lo, ACT);
    gemm_mma<false><<<gP, blk>>>(cx_hi, cx_lo, w_hi + WOFF_O, w_lo + WOFF_O, bo, tmp, DM, DM);
    ln_kernel<<<N_TOK, 128>>>(h, tmp, ln1g, ln1b, h1);

    convert_split<<<ACT / 1024, 256>>>(h1, h1_hi, h1_lo, ACT);
    gemm_mma<true ><<<gF1, blk>>>(h1_hi, h1_lo, w_hi + WOFF_1, w_lo + WOFF_1, b1, ff, DFF, DM);

    convert_split<<<FFE / 1024, 256>>>(ff, ff_hi, ff_lo, FFE);
    gemm_mma<false><<<gP, blk>>>(ff_hi, ff_lo, w_hi + WOFF_2, w_lo + WOFF_2, b2, tmp, DM, DFF);
    ln_kernel<<<N_TOK, 128>>>(h1, tmp, ln2g, ln2b, out);
}